// round 9
// baseline (speedup 1.0000x reference)
#include <cuda_runtime.h>
#include <cuda_fp16.h>

// Problem constants (fixed by the dataset)
#define MAX_N 100000
#define D 128            // D_IN == D_OUT == 128
#define RPB 128          // rows per GEMM block
#define CAP 64           // padded-CSR bucket capacity per node
#define OVF_MAX 65536    // overflow list capacity (expected use: 0)

// Scratch (device globals — no dynamic allocation allowed)
__device__ __align__(16) __half g_y[(size_t)MAX_N * D];  // dinv[r]*(X@W)[r], fp16
__device__ __align__(16) __half g_wt[D * D];             // W transposed [n][k], fp16
__device__ int    g_cnt[MAX_N];                    // in-degree / fill cursor
__device__ int    g_bucket[(size_t)MAX_N * CAP];   // source ids, grouped by dest
__device__ int    g_ovf_cnt;
__device__ int2   g_ovf[OVF_MAX];                  // (r, c) spill edges

// ---------------------------------------------------------------------------
// 0) fused: zero cursors + one-time W transpose/convert g_wt[n][k] = (half)W[k][n]
__global__ void k_prep(const float* __restrict__ w, int N) {
    int idx = blockIdx.x * blockDim.x + threadIdx.x;
    if (idx < N) g_cnt[idx] = 0;
    if (idx == 0) g_ovf_cnt = 0;
    if (idx < D * D / 2) {
        int kk = idx & 63;            // k-pair index (k = 2*kk)
        int n  = idx >> 6;
        float w0 = w[(2 * kk + 0) * D + n];
        float w1 = w[(2 * kk + 1) * D + n];
        __half2 h = __floats2half2_rn(w0, w1);
        *(__half2*)(g_wt + n * D + 2 * kk) = h;
    }
}

// 1) build padded CSR: cursor atomicAdd gives degree AND slot in one pass
__global__ void k_fill(const int* __restrict__ row,
                       const int* __restrict__ col, int E, int N) {
    int e = blockIdx.x * blockDim.x + threadIdx.x;
    if (e >= E) return;
    int r = row[e];
    int c = col[e];
    if (r == c) return;                                   // self-loop weight 0
    if ((unsigned)r >= (unsigned)N || (unsigned)c >= (unsigned)N) return;
    int slot = atomicAdd(&g_cnt[c], 1);
    if (slot < CAP) {
        g_bucket[(size_t)c * CAP + slot] = r;
    } else {
        int o = atomicAdd(&g_ovf_cnt, 1);
        if (o < OVF_MAX) g_ovf[o] = make_int2(r, c);
    }
}

// ---------------------------------------------------------------------------
// 2) Tensor-core GEMM (mma.sync m16n8k16 fp16 -> fp32):
//    g_y[r] = (half) dinv[r] * (X@W)[r]
//    Block: 256 threads = 8 warps; 128 rows x 128 cols per block.
//    Smem (48KB static): Xs 128x256B fp16 (32KB) + Wt half-tile 64x256B (16KB),
//    2 passes over n-halves reuse Xs. XOR swizzle (byte ^ ((row&7)<<4)).
//    Warp w: rows [w*16, w*16+16); per pass 8 ntiles x acc[4].
__device__ __forceinline__ void mma16816(float* d, unsigned a0, unsigned a1,
                                         unsigned a2, unsigned a3,
                                         unsigned b0, unsigned b1) {
    asm volatile(
        "mma.sync.aligned.m16n8k16.row.col.f32.f16.f16.f32 "
        "{%0,%1,%2,%3}, {%4,%5,%6,%7}, {%8,%9}, {%0,%1,%2,%3};"
        : "+f"(d[0]), "+f"(d[1]), "+f"(d[2]), "+f"(d[3])
        : "r"(a0), "r"(a1), "r"(a2), "r"(a3), "r"(b0), "r"(b1));
}

__global__ void k_gemm(const float* __restrict__ x, int N) {
    __shared__ __align__(16) unsigned char sm[49152];
    // Xs: bytes [0, 32768): local row r -> r*256
    // Wt: bytes [32768, 49152): local n (0..63) -> 32768 + n*256

    int tid = threadIdx.x;
    int lane = tid & 31;
    int w = tid >> 5;
    int block_row = blockIdx.x * RPB;

    // stage Xs: 128 rows x 32 float4 = 4096 chunks, 16 per thread
    const float4* x4 = (const float4*)x;
#pragma unroll
    for (int i = 0; i < 16; i++) {
        int idx = tid + 256 * i;            // idx = r*32 + q
        int r = idx >> 5, q = idx & 31;
        int gr = block_row + r;
        float4 v = make_float4(0.f, 0.f, 0.f, 0.f);
        if (gr < N) v = x4[(size_t)gr * 32 + q];
        __half2 h0 = __floats2half2_rn(v.x, v.y);
        __half2 h1 = __floats2half2_rn(v.z, v.w);
        uint2 pk;
        pk.x = *(unsigned*)&h0;
        pk.y = *(unsigned*)&h1;
        int byte = r * 256 + q * 8;
        *(uint2*)(sm + (byte ^ ((r & 7) << 4))) = pk;
    }

    int g  = lane >> 2;        // 0..7
    int t4 = lane & 3;         // 0..3
    int swz = g << 4;

    int r0 = block_row + w * 16 + g;
    int r1 = r0 + 8;
    float s0 = (r0 < N) ? rsqrtf((float)(g_cnt[r0] + 1)) : 0.f;
    float s1 = (r1 < N) ? rsqrtf((float)(g_cnt[r1] + 1)) : 0.f;

    const unsigned char* xrow0 = sm + (w * 16 + g) * 256;
    const unsigned char* xrow8 = xrow0 + 8 * 256;
    const uint4* wt4 = (const uint4*)g_wt;      // row n = 16 uint4

#pragma unroll
    for (int p = 0; p < 2; p++) {
        __syncthreads();   // Xs ready (p=0) / prior-pass Wt reads done (p=1)
        // stage Wt half: n in [p*64, p*64+64): 1024 uint4, 4 per thread
#pragma unroll
        for (int i = 0; i < 4; i++) {
            int idx = tid + 256 * i;        // idx = nl*16 + c
            int nl = idx >> 4, c = idx & 15;
            uint4 v = wt4[(p * 64 + nl) * 16 + c];
            *(uint4*)(sm + 32768 + nl * 256 + ((c ^ (nl & 7)) << 4)) = v;
        }
        __syncthreads();

        float acc[8][4];
#pragma unroll
        for (int nt = 0; nt < 8; nt++)
#pragma unroll
            for (int j = 0; j < 4; j++) acc[nt][j] = 0.f;

#pragma unroll
        for (int ks = 0; ks < 8; ks++) {
            int kb = ks * 32 + t4 * 4;
            unsigned a0 = *(const unsigned*)(xrow0 + ( kb       ^ swz));
            unsigned a1 = *(const unsigned*)(xrow8 + ( kb       ^ swz));
            unsigned a2 = *(const unsigned*)(xrow0 + ((kb + 16) ^ swz));
            unsigned a3 = *(const unsigned*)(xrow8 + ((kb + 16) ^ swz));
#pragma unroll
            for (int nt = 0; nt < 8; nt++) {
                const unsigned char* wp = sm + 32768 + (nt * 8 + g) * 256;
                unsigned b0 = *(const unsigned*)(wp + ( kb       ^ swz));
                unsigned b1 = *(const unsigned*)(wp + ((kb + 16) ^ swz));
                mma16816(acc[nt], a0, a1, a2, a3, b0, b1);
            }
        }

        // epilogue for this n-half
#pragma unroll
        for (int nt = 0; nt < 8; nt++) {
            int col = p * 64 + nt * 8 + t4 * 2;
            if (r0 < N) {
                __half2 h = __floats2half2_rn(acc[nt][0] * s0, acc[nt][1] * s0);
                *(__half2*)(g_y + (size_t)r0 * D + col) = h;
            }
            if (r1 < N) {
                __half2 h = __floats2half2_rn(acc[nt][2] * s1, acc[nt][3] * s1);
                *(__half2*)(g_y + (size_t)r1 * D + col) = h;
            }
        }
    }
}

// ---------------------------------------------------------------------------
// helper: accumulate one fp16 message row into fp32 acc
__device__ __forceinline__ void acc_row(float4& acc, int r, int lane) {
    float2 raw = __ldg((const float2*)(g_y + (size_t)r * D) + lane);
    unsigned u0 = __float_as_uint(raw.x);
    unsigned u1 = __float_as_uint(raw.y);
    float2 f0 = __half22float2(*(__half2*)&u0);
    float2 f1 = __half22float2(*(__half2*)&u1);
    acc.x += f0.x; acc.y += f0.y; acc.z += f1.x; acc.w += f1.y;
}

// 3) per-destination accumulate: one warp per node.
//    out[c] = bias + dinv_c * (sum_r y[r] + y[c])   -- out is WRITE-ONLY.
__global__ void k_acc(const float* __restrict__ bias,
                      float* __restrict__ out, int N) {
    int lane = threadIdx.x & 31;
    int c = (blockIdx.x * blockDim.x + threadIdx.x) >> 5;
    if (c >= N) return;

    int cnt_full = g_cnt[c];
    int cnt = cnt_full > CAP ? CAP : cnt_full;   // spill handled by k_spill

    float4 acc = make_float4(0.f, 0.f, 0.f, 0.f);
    acc_row(acc, c, lane);                        // self-loop message

    const int* base = g_bucket + (size_t)c * CAP;
    for (int b = 0; b < cnt; b += 32) {
        int m = cnt - b; if (m > 32) m = 32;
        int ids = __ldg(base + b + lane);   // coalesced 128B; garbage past m OK
        int j = 0;
        for (; j + 8 <= m; j += 8) {        // 8 independent gathers in flight
            int r0 = __shfl_sync(0xffffffffu, ids, j + 0);
            int r1 = __shfl_sync(0xffffffffu, ids, j + 1);
            int r2 = __shfl_sync(0xffffffffu, ids, j + 2);
            int r3 = __shfl_sync(0xffffffffu, ids, j + 3);
            int r4 = __shfl_sync(0xffffffffu, ids, j + 4);
            int r5 = __shfl_sync(0xffffffffu, ids, j + 5);
            int r6 = __shfl_sync(0xffffffffu, ids, j + 6);
            int r7 = __shfl_sync(0xffffffffu, ids, j + 7);
            acc_row(acc, r0, lane); acc_row(acc, r1, lane);
            acc_row(acc, r2, lane); acc_row(acc, r3, lane);
            acc_row(acc, r4, lane); acc_row(acc, r5, lane);
            acc_row(acc, r6, lane); acc_row(acc, r7, lane);
        }
        for (; j + 4 <= m; j += 4) {
            int r0 = __shfl_sync(0xffffffffu, ids, j + 0);
            int r1 = __shfl_sync(0xffffffffu, ids, j + 1);
            int r2 = __shfl_sync(0xffffffffu, ids, j + 2);
            int r3 = __shfl_sync(0xffffffffu, ids, j + 3);
            acc_row(acc, r0, lane); acc_row(acc, r1, lane);
            acc_row(acc, r2, lane); acc_row(acc, r3, lane);
        }
        for (; j < m; j++) {
            int r0 = __shfl_sync(0xffffffffu, ids, j);
            acc_row(acc, r0, lane);
        }
    }

    float s = rsqrtf((float)(cnt_full + 1));
    float4 bv = __ldg((const float4*)bias + lane);
    ((float4*)(out + (size_t)c * D))[lane] =
        make_float4(fmaf(s, acc.x, bv.x), fmaf(s, acc.y, bv.y),
                    fmaf(s, acc.z, bv.z), fmaf(s, acc.w, bv.w));
}

// 4) spill edges (expected 0): warp per edge, atomic vector RED.
__global__ void k_spill(float* __restrict__ out, int N) {
    int lane = threadIdx.x & 31;
    int gw = (blockIdx.x * blockDim.x + threadIdx.x) >> 5;
    int nw = (gridDim.x * blockDim.x) >> 5;
    int ovf = g_ovf_cnt;
    if (ovf > OVF_MAX) ovf = OVF_MAX;
    for (int o = gw; o < ovf; o += nw) {
        int2 e = g_ovf[o];
        float norm = rsqrtf((float)(g_cnt[e.y] + 1));  // g_y already has dinv[r]
        float2 raw = __ldg((const float2*)(g_y + (size_t)e.x * D) + lane);
        unsigned u0 = __float_as_uint(raw.x);
        unsigned u1 = __float_as_uint(raw.y);
        float2 f0 = __half22float2(*(__half2*)&u0);
        float2 f1 = __half22float2(*(__half2*)&u1);
        float4 m = make_float4(f0.x * norm, f0.y * norm, f1.x * norm, f1.y * norm);
        atomicAdd((float4*)(out + (size_t)e.y * D) + lane, m);
    }
}

extern "C" void kernel_launch(void* const* d_in, const int* in_sizes, int n_in,
                              void* d_out, int out_size) {
    const float* x    = (const float*)d_in[0];
    const int*   ei   = (const int*)d_in[1];     // int32 edge_index [2, E]
    const float* w    = (const float*)d_in[2];
    const float* bias = (const float*)d_in[3];
    float*       out  = (float*)d_out;

    int N = in_sizes[0] / D;
    int E = in_sizes[1] / 2;
    const int* row = ei;
    const int* col = ei + E;

    k_prep<<<(N + 255) / 256, 256>>>(w, N);
    k_fill<<<(E + 255) / 256, 256>>>(row, col, E, N);
    k_gemm<<<(N + RPB - 1) / RPB, 256>>>(x, N);
    k_acc<<<(N * 32 + 255) / 256, 256>>>(bias, out, N);
    k_spill<<<64, 256>>>(out, N);
}

// round 10
// speedup vs baseline: 1.1993x; 1.1993x over previous
#include <cuda_runtime.h>
#include <cuda_fp16.h>

// Problem constants (fixed by the dataset)
#define MAX_N 100000
#define D 128            // D_IN == D_OUT == 128
#define ROWS_PER_BLK 64
#define CAP 64           // padded-CSR bucket capacity per node
#define OVF_MAX 65536    // overflow list capacity (expected use: 0)

// Scratch (device globals — no dynamic allocation allowed)
__device__ __align__(16) __half g_y[(size_t)MAX_N * D];  // dinv[r]*(X@W)[r], fp16
__device__ __align__(16) __half g_wt[D * D];             // W transposed [n][k], fp16
__device__ int    g_cnt[MAX_N];                    // in-degree / fill cursor
__device__ int    g_bucket[(size_t)MAX_N * CAP];   // source ids, grouped by dest
__device__ int    g_ovf_cnt;
__device__ int2   g_ovf[OVF_MAX];                  // (r, c) spill edges

// ---------------------------------------------------------------------------
// 0) fused: zero cursors + one-time W transpose/convert g_wt[n][k] = (half)W[k][n]
__global__ void k_prep(const float* __restrict__ w, int N) {
    int idx = blockIdx.x * blockDim.x + threadIdx.x;
    if (idx < N) g_cnt[idx] = 0;
    if (idx == 0) g_ovf_cnt = 0;
    if (idx < D * D / 2) {
        int kk = idx & 63;            // k-pair index (k = 2*kk)
        int n  = idx >> 6;
        float w0 = w[(2 * kk + 0) * D + n];
        float w1 = w[(2 * kk + 1) * D + n];
        __half2 h = __floats2half2_rn(w0, w1);
        *(__half2*)(g_wt + n * D + 2 * kk) = h;
    }
}

// 1) build padded CSR: cursor atomicAdd gives degree AND slot in one pass
__global__ void k_fill(const int* __restrict__ row,
                       const int* __restrict__ col, int E, int N) {
    int e = blockIdx.x * blockDim.x + threadIdx.x;
    if (e >= E) return;
    int r = row[e];
    int c = col[e];
    if (r == c) return;                                   // self-loop weight 0
    if ((unsigned)r >= (unsigned)N || (unsigned)c >= (unsigned)N) return;
    int slot = atomicAdd(&g_cnt[c], 1);
    if (slot < CAP) {
        g_bucket[(size_t)c * CAP + slot] = r;
    } else {
        int o = atomicAdd(&g_ovf_cnt, 1);
        if (o < OVF_MAX) g_ovf[o] = make_int2(r, c);
    }
}

// ---------------------------------------------------------------------------
// 2) Tensor-core GEMM (mma.sync m16n8k16 fp16 -> fp32)  [R8 version, proven]
//    g_y[r] = (half) dinv[r] * (X@W)[r]
//    Block: 128 threads = 4 warps; 64 rows x 128 cols per block.
__device__ __forceinline__ void mma16816(float* d, unsigned a0, unsigned a1,
                                         unsigned a2, unsigned a3,
                                         unsigned b0, unsigned b1) {
    asm volatile(
        "mma.sync.aligned.m16n8k16.row.col.f32.f16.f16.f32 "
        "{%0,%1,%2,%3}, {%4,%5,%6,%7}, {%8,%9}, {%0,%1,%2,%3};"
        : "+f"(d[0]), "+f"(d[1]), "+f"(d[2]), "+f"(d[3])
        : "r"(a0), "r"(a1), "r"(a2), "r"(a3), "r"(b0), "r"(b1));
}

__global__ void k_gemm(const float* __restrict__ x, int N) {
    __shared__ __align__(16) unsigned char sm[49152];
    // Xs: bytes [0, 16384): 64 rows x 256B   (row = local row)
    // Wt: bytes [16384, 49152): 128 rows x 256B (row = n)

    int tid = threadIdx.x;
    int lane = tid & 31;
    int w = tid >> 5;
    int block_row = blockIdx.x * ROWS_PER_BLK;

    const uint4* wt4 = (const uint4*)g_wt;
#pragma unroll
    for (int i = 0; i < 16; i++) {
        int idx = tid + 128 * i;            // idx = n*16 + c
        int n = idx >> 4, c = idx & 15;
        uint4 v = wt4[idx];
        *(uint4*)(sm + 16384 + n * 256 + ((c ^ (n & 7)) << 4)) = v;
    }

    const float4* x4 = (const float4*)x;
#pragma unroll
    for (int i = 0; i < 16; i++) {
        int idx = tid + 128 * i;            // idx = r*32 + q
        int r = idx >> 5, q = idx & 31;
        int gr = block_row + r;
        float4 v = make_float4(0.f, 0.f, 0.f, 0.f);
        if (gr < N) v = x4[(size_t)gr * 32 + q];
        __half2 h0 = __floats2half2_rn(v.x, v.y);
        __half2 h1 = __floats2half2_rn(v.z, v.w);
        uint2 p;
        p.x = *(unsigned*)&h0;
        p.y = *(unsigned*)&h1;
        int byte = r * 256 + q * 8;
        *(uint2*)(sm + (byte ^ ((r & 7) << 4))) = p;
    }
    __syncthreads();

    int g  = lane >> 2;        // 0..7
    int t4 = lane & 3;         // 0..3
    int swz = g << 4;

    float acc[16][4];
#pragma unroll
    for (int nt = 0; nt < 16; nt++)
#pragma unroll
        for (int j = 0; j < 4; j++) acc[nt][j] = 0.f;

    const unsigned char* xrow0 = sm + (w * 16 + g) * 256;
    const unsigned char* xrow8 = xrow0 + 8 * 256;
    const unsigned char* wbase = sm + 16384 + g * 256;

#pragma unroll
    for (int ks = 0; ks < 8; ks++) {
        int kb = ks * 32 + t4 * 4;
        unsigned a0 = *(const unsigned*)(xrow0 + ( kb       ^ swz));
        unsigned a1 = *(const unsigned*)(xrow8 + ( kb       ^ swz));
        unsigned a2 = *(const unsigned*)(xrow0 + ((kb + 16) ^ swz));
        unsigned a3 = *(const unsigned*)(xrow8 + ((kb + 16) ^ swz));
#pragma unroll
        for (int nt = 0; nt < 16; nt++) {
            const unsigned char* wp = wbase + nt * 8 * 256;
            unsigned b0 = *(const unsigned*)(wp + ( kb       ^ swz));
            unsigned b1 = *(const unsigned*)(wp + ((kb + 16) ^ swz));
            mma16816(acc[nt], a0, a1, a2, a3, b0, b1);
        }
    }

    int r0 = block_row + w * 16 + g;
    int r1 = r0 + 8;
    float s0 = 0.f, s1 = 0.f;
    if (r0 < N) s0 = rsqrtf((float)(g_cnt[r0] + 1));
    if (r1 < N) s1 = rsqrtf((float)(g_cnt[r1] + 1));

#pragma unroll
    for (int nt = 0; nt < 16; nt++) {
        int col = nt * 8 + t4 * 2;
        if (r0 < N) {
            __half2 h = __floats2half2_rn(acc[nt][0] * s0, acc[nt][1] * s0);
            *(__half2*)(g_y + (size_t)r0 * D + col) = h;
        }
        if (r1 < N) {
            __half2 h = __floats2half2_rn(acc[nt][2] * s1, acc[nt][3] * s1);
            *(__half2*)(g_y + (size_t)r1 * D + col) = h;
        }
    }
}

// ---------------------------------------------------------------------------
// helper: acc[0..7] += sel * fp16x8(raw)
__device__ __forceinline__ void acc_row16(float* acc, float4 raw, float sel) {
    unsigned u0 = __float_as_uint(raw.x);
    unsigned u1 = __float_as_uint(raw.y);
    unsigned u2 = __float_as_uint(raw.z);
    unsigned u3 = __float_as_uint(raw.w);
    float2 f0 = __half22float2(*(__half2*)&u0);
    float2 f1 = __half22float2(*(__half2*)&u1);
    float2 f2 = __half22float2(*(__half2*)&u2);
    float2 f3 = __half22float2(*(__half2*)&u3);
    acc[0] = fmaf(sel, f0.x, acc[0]); acc[1] = fmaf(sel, f0.y, acc[1]);
    acc[2] = fmaf(sel, f1.x, acc[2]); acc[3] = fmaf(sel, f1.y, acc[3]);
    acc[4] = fmaf(sel, f2.x, acc[4]); acc[5] = fmaf(sel, f2.y, acc[5]);
    acc[6] = fmaf(sel, f3.x, acc[6]); acc[7] = fmaf(sel, f3.y, acc[7]);
}

// 3) per-destination accumulate: TWO nodes per warp, 16 lanes per node row.
//    Each LDG.128 warp-instruction gathers 512B (two rows) -> half the
//    load instructions and half the warps of the 1-node version.
//    out[c] = bias + dinv_c * (sum_r y[r] + y[c])   -- out WRITE-ONLY.
//    Uniform control flow: loop to max(cnt0,cnt1), 0/1 multiplier masks
//    lanes past their own cnt (stale bucket ids are in-bounds, loads safe).
__global__ void k_acc(const float* __restrict__ bias,
                      float* __restrict__ out, int N) {
    int lane = threadIdx.x & 31;
    int hl   = lane & 15;          // lane within half-warp
    int wid  = (blockIdx.x * blockDim.x + threadIdx.x) >> 5;
    int c0 = 2 * wid;
    if (c0 >= N) return;
    int c = c0 + (lane >> 4);
    if (c >= N) c = c0;            // odd-N tail: both halves same node (benign)

    int cnt_full = g_cnt[c];
    int cnt = cnt_full > CAP ? CAP : cnt_full;   // spill handled by k_spill
    int maxcnt = max(cnt, __shfl_xor_sync(0xffffffffu, cnt, 16));

    float acc[8];
#pragma unroll
    for (int i = 0; i < 8; i++) acc[i] = 0.f;

    // self-loop message
    acc_row16(acc, __ldg((const float4*)(g_y + (size_t)c * D) + hl), 1.f);

    const int* base = g_bucket + (size_t)c * CAP;
    for (int k = 0; k * 16 < maxcnt; k++) {
        int ids = __ldg(base + k * 16 + hl);   // coalesced; stale ids in-bounds
#pragma unroll
        for (int j = 0; j < 16; j += 4) {
            if (k * 16 + j >= maxcnt) break;   // warp-uniform
            int r0 = __shfl_sync(0xffffffffu, ids, j + 0, 16);
            int r1 = __shfl_sync(0xffffffffu, ids, j + 1, 16);
            int r2 = __shfl_sync(0xffffffffu, ids, j + 2, 16);
            int r3 = __shfl_sync(0xffffffffu, ids, j + 3, 16);
            float4 g0 = __ldg((const float4*)(g_y + (size_t)r0 * D) + hl);
            float4 g1 = __ldg((const float4*)(g_y + (size_t)r1 * D) + hl);
            float4 g2 = __ldg((const float4*)(g_y + (size_t)r2 * D) + hl);
            float4 g3 = __ldg((const float4*)(g_y + (size_t)r3 * D) + hl);
            int b = k * 16 + j;
            acc_row16(acc, g0, b + 0 < cnt ? 1.f : 0.f);
            acc_row16(acc, g1, b + 1 < cnt ? 1.f : 0.f);
            acc_row16(acc, g2, b + 2 < cnt ? 1.f : 0.f);
            acc_row16(acc, g3, b + 3 < cnt ? 1.f : 0.f);
        }
    }

    float s = rsqrtf((float)(cnt_full + 1));
    float4 bv0 = __ldg((const float4*)bias + 2 * hl);
    float4 bv1 = __ldg((const float4*)bias + 2 * hl + 1);
    float4* o4 = (float4*)(out + (size_t)c * D);
    o4[2 * hl] = make_float4(fmaf(s, acc[0], bv0.x), fmaf(s, acc[1], bv0.y),
                             fmaf(s, acc[2], bv0.z), fmaf(s, acc[3], bv0.w));
    o4[2 * hl + 1] = make_float4(fmaf(s, acc[4], bv1.x), fmaf(s, acc[5], bv1.y),
                                 fmaf(s, acc[6], bv1.z), fmaf(s, acc[7], bv1.w));
}

// 4) spill edges (expected 0): warp per edge, atomic vector RED.
__global__ void k_spill(float* __restrict__ out, int N) {
    int lane = threadIdx.x & 31;
    int gw = (blockIdx.x * blockDim.x + threadIdx.x) >> 5;
    int nw = (gridDim.x * blockDim.x) >> 5;
    int ovf = g_ovf_cnt;
    if (ovf > OVF_MAX) ovf = OVF_MAX;
    for (int o = gw; o < ovf; o += nw) {
        int2 e = g_ovf[o];
        float norm = rsqrtf((float)(g_cnt[e.y] + 1));  // g_y already has dinv[r]
        float2 raw = __ldg((const float2*)(g_y + (size_t)e.x * D) + lane);
        unsigned u0 = __float_as_uint(raw.x);
        unsigned u1 = __float_as_uint(raw.y);
        float2 f0 = __half22float2(*(__half2*)&u0);
        float2 f1 = __half22float2(*(__half2*)&u1);
        float4 m = make_float4(f0.x * norm, f0.y * norm, f1.x * norm, f1.y * norm);
        atomicAdd((float4*)(out + (size_t)e.y * D) + lane, m);
    }
}

extern "C" void kernel_launch(void* const* d_in, const int* in_sizes, int n_in,
                              void* d_out, int out_size) {
    const float* x    = (const float*)d_in[0];
    const int*   ei   = (const int*)d_in[1];     // int32 edge_index [2, E]
    const float* w    = (const float*)d_in[2];
    const float* bias = (const float*)d_in[3];
    float*       out  = (float*)d_out;

    int N = in_sizes[0] / D;
    int E = in_sizes[1] / 2;
    const int* row = ei;
    const int* col = ei + E;

    k_prep<<<(N + 255) / 256, 256>>>(w, N);
    k_fill<<<(E + 255) / 256, 256>>>(row, col, E, N);
    k_gemm<<<(N + ROWS_PER_BLK - 1) / ROWS_PER_BLK, 128>>>(x, N);
    int warps = (N + 1) / 2;
    k_acc<<<(warps * 32 + 255) / 256, 256>>>(bias, out, N);
    k_spill<<<64, 256>>>(out, N);
}

// round 11
// speedup vs baseline: 1.2260x; 1.0222x over previous
#include <cuda_runtime.h>
#include <cuda_fp16.h>

// Problem constants (fixed by the dataset)
#define MAX_N 100000
#define D 128            // D_IN == D_OUT == 128
#define ROWS_PER_BLK 64
#define CAP 64           // padded-CSR bucket capacity per node
#define OVF_MAX 65536    // overflow list capacity (expected use: 0)
#define GEMM_GRID 296    // 2 blocks/SM x 148 SMs (persistent)

// Scratch (device globals — no dynamic allocation allowed)
__device__ __align__(16) __half g_y[(size_t)MAX_N * D];  // dinv[r]*(X@W)[r], fp16
__device__ __align__(16) __half g_wt[D * D];             // W transposed [n][k], fp16
__device__ int    g_cnt[MAX_N];                    // in-degree / fill cursor
__device__ int    g_bucket[(size_t)MAX_N * CAP];   // source ids, grouped by dest
__device__ int    g_ovf_cnt;
__device__ int2   g_ovf[OVF_MAX];                  // (r, c) spill edges

// ---------------------------------------------------------------------------
// 0) fused: zero cursors + one-time W transpose/convert g_wt[n][k] = (half)W[k][n]
__global__ void k_prep(const float* __restrict__ w, int N) {
    int idx = blockIdx.x * blockDim.x + threadIdx.x;
    if (idx < N) g_cnt[idx] = 0;
    if (idx == 0) g_ovf_cnt = 0;
    if (idx < D * D / 2) {
        int kk = idx & 63;            // k-pair index (k = 2*kk)
        int n  = idx >> 6;
        float w0 = w[(2 * kk + 0) * D + n];
        float w1 = w[(2 * kk + 1) * D + n];
        __half2 h = __floats2half2_rn(w0, w1);
        *(__half2*)(g_wt + n * D + 2 * kk) = h;
    }
}

// 1) build padded CSR: cursor atomicAdd gives degree AND slot in one pass
__global__ void k_fill(const int* __restrict__ row,
                       const int* __restrict__ col, int E, int N) {
    int e = blockIdx.x * blockDim.x + threadIdx.x;
    if (e >= E) return;
    int r = row[e];
    int c = col[e];
    if (r == c) return;                                   // self-loop weight 0
    if ((unsigned)r >= (unsigned)N || (unsigned)c >= (unsigned)N) return;
    int slot = atomicAdd(&g_cnt[c], 1);
    if (slot < CAP) {
        g_bucket[(size_t)c * CAP + slot] = r;
    } else {
        int o = atomicAdd(&g_ovf_cnt, 1);
        if (o < OVF_MAX) g_ovf[o] = make_int2(r, c);
    }
}

// ---------------------------------------------------------------------------
__device__ __forceinline__ void mma16816(float* d, unsigned a0, unsigned a1,
                                         unsigned a2, unsigned a3,
                                         unsigned b0, unsigned b1) {
    asm volatile(
        "mma.sync.aligned.m16n8k16.row.col.f32.f16.f16.f32 "
        "{%0,%1,%2,%3}, {%4,%5,%6,%7}, {%8,%9}, {%0,%1,%2,%3};"
        : "+f"(d[0]), "+f"(d[1]), "+f"(d[2]), "+f"(d[3])
        : "r"(a0), "r"(a1), "r"(a2), "r"(a3), "r"(b0), "r"(b1));
}

// 2a) PRIMARY GEMM: persistent, cp.async double-buffered.
//    Dynamic smem 96KB: Wt fp16 [0,32KB) + X fp32 buf0 [32KB,64KB) + buf1 [64KB,96KB).
//    X tile: 64 rows x 512B fp32, 16B-granule swizzle (granule ^ (row&7)).
//    A-fragments converted fp32->fp16 at LDS time; B path identical to R8.
__global__ void __launch_bounds__(128, 2) k_gemm_pipe(const float* __restrict__ x,
                                                      int N, int ntiles) {
    extern __shared__ __align__(16) unsigned char dsm[];

    int tid = threadIdx.x;
    int lane = tid & 31;
    int w = tid >> 5;

    // stage Wt once per block (fp16, swizzled) at dsm[0, 32768)
    const uint4* wt4 = (const uint4*)g_wt;
#pragma unroll
    for (int i = 0; i < 16; i++) {
        int idx = tid + 128 * i;            // idx = n*16 + c
        int n = idx >> 4, c = idx & 15;
        uint4 v = wt4[idx];
        *(uint4*)(dsm + n * 256 + ((c ^ (n & 7)) << 4)) = v;
    }

    unsigned xb[2];
    xb[0] = (unsigned)__cvta_generic_to_shared(dsm + 32768);
    xb[1] = (unsigned)__cvta_generic_to_shared(dsm + 65536);

    // stage one 64-row fp32 tile into buffer b via cp.async (2048 x 16B chunks)
    auto stage = [&](int b, int tile) {
#pragma unroll
        for (int i = 0; i < 16; i++) {
            int idx = tid + 128 * i;
            int r = idx >> 5, q = idx & 31;
            int gr = tile * ROWS_PER_BLK + r;
            if (gr > N - 1) gr = N - 1;          // clamp: epilogue drops r>=N
            const float* src = x + (size_t)gr * D + q * 4;
            unsigned dst = xb[b] + r * 512 + ((q ^ (r & 7)) << 4);
            asm volatile("cp.async.cg.shared.global [%0], [%1], 16;"
                         :: "r"(dst), "l"(src));
        }
    };

    int g  = lane >> 2;        // 0..7
    int t4 = lane & 3;         // 0..3
    unsigned swz = (unsigned)g << 4;

    int t = blockIdx.x;
    if (t < ntiles) stage(0, t);
    asm volatile("cp.async.commit_group;");

    int buf = 0;
    for (; t < ntiles; t += GEMM_GRID) {
        int tn = t + GEMM_GRID;
        if (tn < ntiles) stage(buf ^ 1, tn);     // prefetch next tile
        asm volatile("cp.async.commit_group;");
        asm volatile("cp.async.wait_group 1;");  // current tile landed
        __syncthreads();                          // (also orders Wt stores, 1st iter)

        const unsigned char* xr0 =
            dsm + 32768 + buf * 32768 + (w * 16 + g) * 512;
        const unsigned char* xr8 = xr0 + 8 * 512;

        float acc[16][4];
#pragma unroll
        for (int nt = 0; nt < 16; nt++)
#pragma unroll
            for (int j = 0; j < 4; j++) acc[nt][j] = 0.f;

#pragma unroll
        for (int ks = 0; ks < 8; ks++) {
            // A: fp32 pairs at k = ks*16 + t4*2 (+8), swizzled 16B granules
            int o0 = ks * 64 + t4 * 8;
            int o2 = o0 + 32;
            int p0 = (int)(((unsigned)(o0 & ~15) ^ swz) | (unsigned)(o0 & 15));
            int p2 = (int)(((unsigned)(o2 & ~15) ^ swz) | (unsigned)(o2 & 15));
            float2 f0 = *(const float2*)(xr0 + p0);
            float2 f1 = *(const float2*)(xr8 + p0);
            float2 f2 = *(const float2*)(xr0 + p2);
            float2 f3 = *(const float2*)(xr8 + p2);
            __half2 h0 = __floats2half2_rn(f0.x, f0.y);
            __half2 h1 = __floats2half2_rn(f1.x, f1.y);
            __half2 h2 = __floats2half2_rn(f2.x, f2.y);
            __half2 h3 = __floats2half2_rn(f3.x, f3.y);
            unsigned a0 = *(unsigned*)&h0;
            unsigned a1 = *(unsigned*)&h1;
            unsigned a2 = *(unsigned*)&h2;
            unsigned a3 = *(unsigned*)&h3;

            int kb = ks * 32 + t4 * 4;           // B byte offset (fp16 path)
#pragma unroll
            for (int nt = 0; nt < 16; nt++) {
                const unsigned char* wp = dsm + (nt * 8 + g) * 256;
                unsigned b0 = *(const unsigned*)(wp + ( kb       ^ swz));
                unsigned b1 = *(const unsigned*)(wp + ((kb + 16) ^ swz));
                mma16816(acc[nt], a0, a1, a2, a3, b0, b1);
            }
        }

        // epilogue: y = (half)(dinv * acc)
        int block_row = t * ROWS_PER_BLK;
        int r0 = block_row + w * 16 + g;
        int r1 = r0 + 8;
        float s0 = (r0 < N) ? rsqrtf((float)(g_cnt[r0] + 1)) : 0.f;
        float s1 = (r1 < N) ? rsqrtf((float)(g_cnt[r1] + 1)) : 0.f;
#pragma unroll
        for (int nt = 0; nt < 16; nt++) {
            int col = nt * 8 + t4 * 2;
            if (r0 < N) {
                __half2 h = __floats2half2_rn(acc[nt][0] * s0, acc[nt][1] * s0);
                *(__half2*)(g_y + (size_t)r0 * D + col) = h;
            }
            if (r1 < N) {
                __half2 h = __floats2half2_rn(acc[nt][2] * s1, acc[nt][3] * s1);
                *(__half2*)(g_y + (size_t)r1 * D + col) = h;
            }
        }
        __syncthreads();       // all reads of buf done before it is re-staged
        buf ^= 1;
    }
}

// 2b) FALLBACK GEMM (proven R8 48KB-static version) — used only if the
//     dynamic-smem attribute call is rejected in this environment.
__global__ void k_gemm48(const float* __restrict__ x, int N) {
    __shared__ __align__(16) unsigned char sm[49152];
    int tid = threadIdx.x;
    int lane = tid & 31;
    int w = tid >> 5;
    int block_row = blockIdx.x * ROWS_PER_BLK;

    const uint4* wt4 = (const uint4*)g_wt;
#pragma unroll
    for (int i = 0; i < 16; i++) {
        int idx = tid + 128 * i;
        int n = idx >> 4, c = idx & 15;
        uint4 v = wt4[idx];
        *(uint4*)(sm + 16384 + n * 256 + ((c ^ (n & 7)) << 4)) = v;
    }
    const float4* x4 = (const float4*)x;
#pragma unroll
    for (int i = 0; i < 16; i++) {
        int idx = tid + 128 * i;
        int r = idx >> 5, q = idx & 31;
        int gr = block_row + r;
        float4 v = make_float4(0.f, 0.f, 0.f, 0.f);
        if (gr < N) v = x4[(size_t)gr * 32 + q];
        __half2 h0 = __floats2half2_rn(v.x, v.y);
        __half2 h1 = __floats2half2_rn(v.z, v.w);
        uint2 p;
        p.x = *(unsigned*)&h0;
        p.y = *(unsigned*)&h1;
        int byte = r * 256 + q * 8;
        *(uint2*)(sm + (byte ^ ((r & 7) << 4))) = p;
    }
    __syncthreads();

    int g = lane >> 2, t4 = lane & 3;
    int swz = g << 4;
    float acc[16][4];
#pragma unroll
    for (int nt = 0; nt < 16; nt++)
#pragma unroll
        for (int j = 0; j < 4; j++) acc[nt][j] = 0.f;

    const unsigned char* xrow0 = sm + (w * 16 + g) * 256;
    const unsigned char* xrow8 = xrow0 + 8 * 256;
    const unsigned char* wbase = sm + 16384 + g * 256;
#pragma unroll
    for (int ks = 0; ks < 8; ks++) {
        int kb = ks * 32 + t4 * 4;
        unsigned a0 = *(const unsigned*)(xrow0 + ( kb       ^ swz));
        unsigned a1 = *(const unsigned*)(xrow8 + ( kb       ^ swz));
        unsigned a2 = *(const unsigned*)(xrow0 + ((kb + 16) ^ swz));
        unsigned a3 = *(const unsigned*)(xrow8 + ((kb + 16) ^ swz));
#pragma unroll
        for (int nt = 0; nt < 16; nt++) {
            const unsigned char* wp = wbase + nt * 8 * 256;
            unsigned b0 = *(const unsigned*)(wp + ( kb       ^ swz));
            unsigned b1 = *(const unsigned*)(wp + ((kb + 16) ^ swz));
            mma16816(acc[nt], a0, a1, a2, a3, b0, b1);
        }
    }
    int r0 = block_row + w * 16 + g;
    int r1 = r0 + 8;
    float s0 = (r0 < N) ? rsqrtf((float)(g_cnt[r0] + 1)) : 0.f;
    float s1 = (r1 < N) ? rsqrtf((float)(g_cnt[r1] + 1)) : 0.f;
#pragma unroll
    for (int nt = 0; nt < 16; nt++) {
        int col = nt * 8 + t4 * 2;
        if (r0 < N) {
            __half2 h = __floats2half2_rn(acc[nt][0] * s0, acc[nt][1] * s0);
            *(__half2*)(g_y + (size_t)r0 * D + col) = h;
        }
        if (r1 < N) {
            __half2 h = __floats2half2_rn(acc[nt][2] * s1, acc[nt][3] * s1);
            *(__half2*)(g_y + (size_t)r1 * D + col) = h;
        }
    }
}

// ---------------------------------------------------------------------------
// helper: acc[0..7] += sel * fp16x8(raw)
__device__ __forceinline__ void acc_row16(float* acc, float4 raw, float sel) {
    unsigned u0 = __float_as_uint(raw.x);
    unsigned u1 = __float_as_uint(raw.y);
    unsigned u2 = __float_as_uint(raw.z);
    unsigned u3 = __float_as_uint(raw.w);
    float2 f0 = __half22float2(*(__half2*)&u0);
    float2 f1 = __half22float2(*(__half2*)&u1);
    float2 f2 = __half22float2(*(__half2*)&u2);
    float2 f3 = __half22float2(*(__half2*)&u3);
    acc[0] = fmaf(sel, f0.x, acc[0]); acc[1] = fmaf(sel, f0.y, acc[1]);
    acc[2] = fmaf(sel, f1.x, acc[2]); acc[3] = fmaf(sel, f1.y, acc[3]);
    acc[4] = fmaf(sel, f2.x, acc[4]); acc[5] = fmaf(sel, f2.y, acc[5]);
    acc[6] = fmaf(sel, f3.x, acc[6]); acc[7] = fmaf(sel, f3.y, acc[7]);
}

// 3) per-destination accumulate: TWO nodes per warp, 16 lanes per node row.
//    out[c] = bias + dinv_c * (sum_r y[r] + y[c])   -- out WRITE-ONLY.   [R10, at roofline]
__global__ void k_acc(const float* __restrict__ bias,
                      float* __restrict__ out, int N) {
    int lane = threadIdx.x & 31;
    int hl   = lane & 15;
    int wid  = (blockIdx.x * blockDim.x + threadIdx.x) >> 5;
    int c0 = 2 * wid;
    if (c0 >= N) return;
    int c = c0 + (lane >> 4);
    if (c >= N) c = c0;

    int cnt_full = g_cnt[c];
    int cnt = cnt_full > CAP ? CAP : cnt_full;
    int maxcnt = max(cnt, __shfl_xor_sync(0xffffffffu, cnt, 16));

    float acc[8];
#pragma unroll
    for (int i = 0; i < 8; i++) acc[i] = 0.f;

    acc_row16(acc, __ldg((const float4*)(g_y + (size_t)c * D) + hl), 1.f);

    const int* base = g_bucket + (size_t)c * CAP;
    for (int k = 0; k * 16 < maxcnt; k++) {
        int ids = __ldg(base + k * 16 + hl);
#pragma unroll
        for (int j = 0; j < 16; j += 4) {
            if (k * 16 + j >= maxcnt) break;   // warp-uniform
            int r0 = __shfl_sync(0xffffffffu, ids, j + 0, 16);
            int r1 = __shfl_sync(0xffffffffu, ids, j + 1, 16);
            int r2 = __shfl_sync(0xffffffffu, ids, j + 2, 16);
            int r3 = __shfl_sync(0xffffffffu, ids, j + 3, 16);
            float4 g0 = __ldg((const float4*)(g_y + (size_t)r0 * D) + hl);
            float4 g1 = __ldg((const float4*)(g_y + (size_t)r1 * D) + hl);
            float4 g2 = __ldg((const float4*)(g_y + (size_t)r2 * D) + hl);
            float4 g3 = __ldg((const float4*)(g_y + (size_t)r3 * D) + hl);
            int b = k * 16 + j;
            acc_row16(acc, g0, b + 0 < cnt ? 1.f : 0.f);
            acc_row16(acc, g1, b + 1 < cnt ? 1.f : 0.f);
            acc_row16(acc, g2, b + 2 < cnt ? 1.f : 0.f);
            acc_row16(acc, g3, b + 3 < cnt ? 1.f : 0.f);
        }
    }

    float s = rsqrtf((float)(cnt_full + 1));
    float4 bv0 = __ldg((const float4*)bias + 2 * hl);
    float4 bv1 = __ldg((const float4*)bias + 2 * hl + 1);
    float4* o4 = (float4*)(out + (size_t)c * D);
    o4[2 * hl] = make_float4(fmaf(s, acc[0], bv0.x), fmaf(s, acc[1], bv0.y),
                             fmaf(s, acc[2], bv0.z), fmaf(s, acc[3], bv0.w));
    o4[2 * hl + 1] = make_float4(fmaf(s, acc[4], bv1.x), fmaf(s, acc[5], bv1.y),
                                 fmaf(s, acc[6], bv1.z), fmaf(s, acc[7], bv1.w));
}

// 4) spill edges (expected 0): warp per edge, atomic vector RED.
__global__ void k_spill(float* __restrict__ out, int N) {
    int lane = threadIdx.x & 31;
    int gw = (blockIdx.x * blockDim.x + threadIdx.x) >> 5;
    int nw = (gridDim.x * blockDim.x) >> 5;
    int ovf = g_ovf_cnt;
    if (ovf > OVF_MAX) ovf = OVF_MAX;
    for (int o = gw; o < ovf; o += nw) {
        int2 e = g_ovf[o];
        float norm = rsqrtf((float)(g_cnt[e.y] + 1));
        float2 raw = __ldg((const float2*)(g_y + (size_t)e.x * D) + lane);
        unsigned u0 = __float_as_uint(raw.x);
        unsigned u1 = __float_as_uint(raw.y);
        float2 f0 = __half22float2(*(__half2*)&u0);
        float2 f1 = __half22float2(*(__half2*)&u1);
        float4 m = make_float4(f0.x * norm, f0.y * norm, f1.x * norm, f1.y * norm);
        atomicAdd((float4*)(out + (size_t)e.y * D) + lane, m);
    }
}

extern "C" void kernel_launch(void* const* d_in, const int* in_sizes, int n_in,
                              void* d_out, int out_size) {
    const float* x    = (const float*)d_in[0];
    const int*   ei   = (const int*)d_in[1];     // int32 edge_index [2, E]
    const float* w    = (const float*)d_in[2];
    const float* bias = (const float*)d_in[3];
    float*       out  = (float*)d_out;

    int N = in_sizes[0] / D;
    int E = in_sizes[1] / 2;
    const int* row = ei;
    const int* col = ei + E;
    int ntiles = (N + ROWS_PER_BLK - 1) / ROWS_PER_BLK;

    k_prep<<<(N + 255) / 256, 256>>>(w, N);
    k_fill<<<(E + 255) / 256, 256>>>(row, col, E, N);

    // Prefer pipelined GEMM (96KB dynamic smem); fall back to 48KB version
    // if the attribute is rejected in this environment. No static guards —
    // the attribute call is made (idempotently) on every invocation.
    cudaError_t rc = cudaFuncSetAttribute(
        k_gemm_pipe, cudaFuncAttributeMaxDynamicSharedMemorySize, 98304);
    if (rc == cudaSuccess) {
        k_gemm_pipe<<<GEMM_GRID, 128, 98304>>>(x, N, ntiles);
    } else {
        (void)cudaGetLastError();   // clear sticky error from rejected attribute
        k_gemm48<<<ntiles, 128>>>(x, N);
    }

    int warps = (N + 1) / 2;
    k_acc<<<(warps * 32 + 255) / 256, 256>>>(bias, out, N);
    k_spill<<<64, 256>>>(out, N);
}